// round 12
// baseline (speedup 1.0000x reference)
#include <cuda_runtime.h>
#include <math.h>
#include <stdint.h>
#include <mma.h>

using namespace nvcuda;

// ---------------------------------------------------------------------------
// InvariantCrossAttention — factorized; 6 launches; main_attn in profile slot 4.
//   Wkc = [ k_w[:, :768] @ mix_w  |  k_w[:,768:] @ lin_cov_w | 0pad ]  [768 x 832]
//   u'[row,h,:] = Q_h[row] @ Wkc_h       (cols 0..767 = u, 768..776 = qc)
//   scores[h,k] = ( feat[k].u + C9[k].qc ) / sqrt(96);  attn stored to gmem
//   g[row,h,:] = sum_k attn feat[k]
//   Vp_h = g_h @ Wv_h^T + (sum_k attn_k Ve[b,k,:])   (epilogue in GEMM)
//   out = Vp @ o_w^T
// R12: __launch_bounds__(256,2) on the merged kernel.  With __sincosf the
// natural live-state is ~80 regs, so the 128-reg cap should give 2 CTAs/SM
// without the spills that killed R8's attempt.
// ---------------------------------------------------------------------------

#define BATCH  2
#define NQ     1024
#define KE     16
#define DM     768
#define DE     128
#define NH     8
#define DHD    96
#define NFREQ  128
#define ENCFF  2048
#define ROWS   (BATCH*NQ)   // 2048
#define UD     832
#define FFBLK  (BATCH*KE)   // 32

static __device__ float g_encqkv[BATCH*KE*3*DE];
static __device__ float g_x1[BATCH*KE*DE];
static __device__ float g_Ve[BATCH*KE*DM];
static __device__ float g_Wkc[DM*UD];
static __device__ float g_Wv[DM*DM];
static __device__ float g_Q[ROWS*DM];
static __device__ float g_u[(size_t)ROWS*NH*UD];
static __device__ float g_gacc[(size_t)ROWS*NH*DM];
static __device__ float g_attn[ROWS*NH*KE];
static __device__ float g_Vp[ROWS*DM];

__device__ __forceinline__ float warpSum(float v) {
#pragma unroll
    for (int o = 16; o > 0; o >>= 1) v += __shfl_xor_sync(0xffffffffu, v, o);
    return v;
}

// ---------------------------------------------------------------------------
// TF32 GEMM body (single-buffered).  TB=0: C=A@B,  TB=1: C=A@B^T.
// EPI=1: writeback adds sum_k attn[m,k]*Ve[b,k,h*96+n]  (Vp GEMM only).
// Block tile 128x64, 8 warps of 32x32, wmma m16n16k8.
// ---------------------------------------------------------------------------
#define GEMM_SMEM_BYTES (8704*4)
#define EPI_SMEM_BYTES  ((8704+1024+2048)*4)

template<int TB, int EPI>
__device__ __forceinline__ void gemm_body(
        const float* __restrict__ A, const float* __restrict__ B,
        float* __restrict__ C,
        int Ndim, int Kdim, int lda, int ldb, int ldc,
        int m0, int n0, int h) {
    extern __shared__ float smem[];
    float* As = smem;               // [128][36]
    float* Bs = smem + 128*36;      // NN: [32][68] ; NT: [64][36]
    float* Cs = smem;               // [128][68] after mainloop

    int tid = threadIdx.x;
    int w = tid >> 5, wm = w >> 1, wn = w & 1;

    wmma::fragment<wmma::accumulator, 16, 16, 8, float> acc[2][2];
#pragma unroll
    for (int i = 0; i < 2; ++i)
#pragma unroll
        for (int j = 0; j < 2; ++j) wmma::fill_fragment(acc[i][j], 0.f);

    int ar = tid >> 3;
    int ac = (tid & 7) * 4;

    for (int k0 = 0; k0 < Kdim; k0 += 32) {
#pragma unroll
        for (int rr = 0; rr < 128; rr += 32) {
            float4 v = *(const float4*)&A[(size_t)(m0 + ar + rr)*lda + k0 + ac];
            v.x = wmma::__float_to_tf32(v.x); v.y = wmma::__float_to_tf32(v.y);
            v.z = wmma::__float_to_tf32(v.z); v.w = wmma::__float_to_tf32(v.w);
            *(float4*)&As[(ar + rr)*36 + ac] = v;
        }
        if (TB == 0) {
            int bk = tid >> 4;
            int bn = (tid & 15) * 4;
#pragma unroll
            for (int kk = 0; kk < 32; kk += 16) {
                float4 v = *(const float4*)&B[(size_t)(k0 + bk + kk)*ldb + n0 + bn];
                v.x = wmma::__float_to_tf32(v.x); v.y = wmma::__float_to_tf32(v.y);
                v.z = wmma::__float_to_tf32(v.z); v.w = wmma::__float_to_tf32(v.w);
                *(float4*)&Bs[(bk + kk)*68 + bn] = v;
            }
        } else {
            int bn = tid >> 3;
            int bc = (tid & 7) * 4;
#pragma unroll
            for (int nn = 0; nn < 64; nn += 32) {
                int n = n0 + bn + nn;
                float4 v = make_float4(0.f, 0.f, 0.f, 0.f);
                if (n < Ndim) {
                    v = *(const float4*)&B[(size_t)n*ldb + k0 + bc];
                    v.x = wmma::__float_to_tf32(v.x); v.y = wmma::__float_to_tf32(v.y);
                    v.z = wmma::__float_to_tf32(v.z); v.w = wmma::__float_to_tf32(v.w);
                }
                *(float4*)&Bs[(bn + nn)*36 + bc] = v;
            }
        }
        __syncthreads();

#pragma unroll
        for (int ks = 0; ks < 4; ++ks) {
            wmma::fragment<wmma::matrix_a, 16, 16, 8, wmma::precision::tf32, wmma::row_major> af[2];
#pragma unroll
            for (int i = 0; i < 2; ++i)
                wmma::load_matrix_sync(af[i], &As[(wm*32 + i*16)*36 + ks*8], 36);
            if (TB == 0) {
                wmma::fragment<wmma::matrix_b, 16, 16, 8, wmma::precision::tf32, wmma::row_major> bf[2];
#pragma unroll
                for (int j = 0; j < 2; ++j)
                    wmma::load_matrix_sync(bf[j], &Bs[(ks*8)*68 + wn*32 + j*16], 68);
#pragma unroll
                for (int i = 0; i < 2; ++i)
#pragma unroll
                    for (int j = 0; j < 2; ++j)
                        wmma::mma_sync(acc[i][j], af[i], bf[j], acc[i][j]);
            } else {
                wmma::fragment<wmma::matrix_b, 16, 16, 8, wmma::precision::tf32, wmma::col_major> bf[2];
#pragma unroll
                for (int j = 0; j < 2; ++j)
                    wmma::load_matrix_sync(bf[j], &Bs[(wn*32 + j*16)*36 + ks*8], 36);
#pragma unroll
                for (int i = 0; i < 2; ++i)
#pragma unroll
                    for (int j = 0; j < 2; ++j)
                        wmma::mma_sync(acc[i][j], af[i], bf[j], acc[i][j]);
            }
        }
        __syncthreads();
    }

#pragma unroll
    for (int i = 0; i < 2; ++i)
#pragma unroll
        for (int j = 0; j < 2; ++j)
            wmma::store_matrix_sync(&Cs[(wm*32 + i*16)*68 + wn*32 + j*16],
                                    acc[i][j], 68, wmma::mem_row_major);
    __syncthreads();

    if (EPI) {
        float* sVe = smem + 8704;         // [16][64]
        float* sAt = smem + 8704 + 1024;  // [128][16]
        int b = m0 >> 10;
        for (int idx = tid; idx < KE*64; idx += 256) {
            int k = idx >> 6, n = idx & 63;
            int gn = n0 + n;
            sVe[idx] = (gn < Ndim) ? g_Ve[(size_t)(b*KE + k)*DM + h*DHD + gn] : 0.f;
        }
        for (int idx = tid; idx < 128*KE; idx += 256) {
            int m = idx >> 4, k = idx & 15;
            sAt[idx] = g_attn[(size_t)(m0 + m)*(NH*KE) + h*KE + k];
        }
        __syncthreads();
        for (int idx = tid; idx < 128*64; idx += 256) {
            int m = idx >> 6, n = idx & 63;
            int gn = n0 + n;
            if (gn < Ndim) {
                float v = Cs[m*68 + n];
#pragma unroll
                for (int k = 0; k < KE; ++k) v += sAt[m*16 + k]*sVe[k*64 + n];
                C[(size_t)(m0 + m)*ldc + gn] = v;
            }
        }
    } else {
        for (int idx = tid; idx < 128*64; idx += 256) {
            int m = idx >> 6, n = idx & 63;
            int gn = n0 + n;
            if (gn < Ndim)
                C[(size_t)(m0 + m)*ldc + gn] = Cs[m*68 + n];
        }
    }
}

template<int TB, int EPI>
__global__ __launch_bounds__(256) void gemm_tf32(
        const float* __restrict__ A, const float* __restrict__ B,
        float* __restrict__ C,
        int Ndim, int Kdim, int lda, int ldb, int ldc,
        long aZ, long bZ, long cZ) {
    gemm_body<TB, EPI>(A + (long)blockIdx.z*aZ, B + (long)blockIdx.z*bZ,
                       C + (long)blockIdx.z*cZ,
                       Ndim, Kdim, lda, ldb, ldc,
                       blockIdx.y*128, blockIdx.x*64, blockIdx.z);
}

// ---------------------------------------------------------------------------
// Launch 1: fused prep — blocks [0,768) wc, [768,840) Wkc, [840,912) Wv,
// [912,1104) Q-GEMM.
// ---------------------------------------------------------------------------
__global__ __launch_bounds__(256) void fused_prep(
        const float* __restrict__ kw, const float* __restrict__ lcw,
        const float* __restrict__ mixw, const float* __restrict__ s,
        const float* __restrict__ qw, const float* __restrict__ vw) {
    int bx = blockIdx.x;
    if (bx < 768) {
        int o = bx;
        int wg = threadIdx.x >> 5, l = threadIdx.x & 31;
        for (int m = wg; m < 9; m += 8) {
            float acc = 0.f;
            for (int j = l; j < DM; j += 32)
                acc += kw[(size_t)o*(2*DM) + DM + j]*lcw[j*9 + m];
            acc = warpSum(acc);
            if (l == 0) g_Wkc[(size_t)o*UD + DM + m] = acc;
        }
    } else if (bx < 840) {
        int idx = bx - 768;
        gemm_body<0,0>(kw, mixw, g_Wkc, DM, DM, 2*DM, DM, UD,
                       (idx/12)*128, (idx%12)*64, 0);
    } else if (bx < 912) {
        int idx = bx - 840;
        gemm_body<0,0>(vw, mixw, g_Wv, DM, DM, DM+DE, DM, DM,
                       (idx/12)*128, (idx%12)*64, 0);
    } else {
        int idx = bx - 912;
        gemm_body<1,0>(s, qw, g_Q, DM, DM, DM, DM, DM,
                       (idx/12)*128, (idx%12)*64, 0);
    }
}

// ---------------------------------------------------------------------------
// Launch 2: fused u-GEMM ([0,1664)) + enc_qkv ([1664,1696))
// ---------------------------------------------------------------------------
__global__ __launch_bounds__(256) void fused_u(
        const float* __restrict__ xin, const float* __restrict__ ew,
        const float* __restrict__ eb) {
    int bx = blockIdx.x;
    if (bx < 1664) {
        int z = bx / 208, rem = bx % 208;
        gemm_body<0,0>(g_Q + z*DHD, g_Wkc + (size_t)z*DHD*UD, g_u + z*UD,
                       UD, DHD, DM, UD, NH*UD, (rem/13)*128, (rem%13)*64, z);
    } else {
        __shared__ float xs[DE];
        int tk = bx - 1664;
        int tid = threadIdx.x, w = tid >> 5, l = tid & 31;
        if (tid < 32) ((float4*)xs)[tid] = ((const float4*)(xin + tk*DE))[tid];
        __syncthreads();
        float4 xr = ((const float4*)xs)[l];
        for (int i = 0; i < 48; ++i) {
            int o = w*48 + i;
            float4 a = ((const float4*)(ew + (size_t)o*DE))[l];
            float dot = warpSum(a.x*xr.x + a.y*xr.y + a.z*xr.z + a.w*xr.w);
            if (l == 0) g_encqkv[tk*3*DE + o] = dot + eb[o];
        }
    }
}

// ---------------------------------------------------------------------------
// Launch 3: encoder self-attn + out proj + residual + LN1   (grid = B)
// ---------------------------------------------------------------------------
__global__ __launch_bounds__(256) void enc_attn_kernel(
        const float* __restrict__ xin, const float* __restrict__ eow,
        const float* __restrict__ eob, const float* __restrict__ g1,
        const float* __restrict__ b1) {
    __shared__ float qkv[KE][3*DE];
    __shared__ float ao[KE][DE];
    __shared__ float y[KE][DE];
    int b = blockIdx.x;
    int tid = threadIdx.x, w = tid >> 5, l = tid & 31;

    for (int idx = tid; idx < KE*3*DE; idx += 256)
        qkv[idx/(3*DE)][idx%(3*DE)] = g_encqkv[b*KE*3*DE + idx];
    __syncthreads();

#pragma unroll
    for (int pi = 0; pi < 8; ++pi) {
        int p = w*8 + pi;
        int h = p >> 4, q = p & 15;
        float qv = qkv[q][h*32 + l];
        float sc[KE];
#pragma unroll
        for (int k = 0; k < KE; ++k) {
            float pr = qv * qkv[k][DE + h*32 + l];
            sc[k] = warpSum(pr) * 0.17677669529f;
        }
        float mx = sc[0];
#pragma unroll
        for (int k = 1; k < KE; ++k) mx = fmaxf(mx, sc[k]);
        float ssum = 0.f;
#pragma unroll
        for (int k = 0; k < KE; ++k) { sc[k] = __expf(sc[k]-mx); ssum += sc[k]; }
        float inv = 1.f/ssum;
        float acc = 0.f;
#pragma unroll
        for (int k = 0; k < KE; ++k) acc += sc[k]*inv * qkv[k][2*DE + h*32 + l];
        ao[q][h*32 + l] = acc;
    }
    __syncthreads();

    for (int i = 0; i < 256; ++i) {
        int j = w*256 + i;
        int q = j >> 7, o = j & 127;
        float4 a = ((const float4*)(eow + (size_t)o*DE))[l];
        float4 x4 = ((const float4*)&ao[q][0])[l];
        float dot = warpSum(a.x*x4.x + a.y*x4.y + a.z*x4.z + a.w*x4.w);
        if (l == 0) y[q][o] = dot + eob[o] + xin[(b*KE + q)*DE + o];
    }
    __syncthreads();

#pragma unroll
    for (int qi = 0; qi < 2; ++qi) {
        int q = w*2 + qi;
        float v0 = y[q][l], v1 = y[q][l+32], v2 = y[q][l+64], v3 = y[q][l+96];
        float mean = warpSum(v0+v1+v2+v3) * (1.f/DE);
        float d0 = v0-mean, d1 = v1-mean, d2 = v2-mean, d3 = v3-mean;
        float var = warpSum(d0*d0+d1*d1+d2*d2+d3*d3) * (1.f/DE);
        float inv = rsqrtf(var + 1e-5f);
        g_x1[(b*KE+q)*DE + l]    = d0*inv*g1[l]    + b1[l];
        g_x1[(b*KE+q)*DE + l+32] = d1*inv*g1[l+32] + b1[l+32];
        g_x1[(b*KE+q)*DE + l+64] = d2*inv*g1[l+64] + b1[l+64];
        g_x1[(b*KE+q)*DE + l+96] = d3*inv*g1[l+96] + b1[l+96];
    }
}

// ---------------------------------------------------------------------------
// enc_ff body (device fn; runs as blocks 0..31 of the merged launch 4)
// ---------------------------------------------------------------------------
__device__ void enc_ff_body(
        int tk,
        const float* __restrict__ l1w, const float* __restrict__ l1b,
        const float* __restrict__ l2w, const float* __restrict__ l2b,
        const float* __restrict__ g2,  const float* __restrict__ b2,
        const float* __restrict__ vw) {
    __shared__ float xs[DE];
    __shared__ float hs[ENCFF];
    __shared__ float es[DE];
    __shared__ float part[2][DE];
    __shared__ float red[8];
    __shared__ float smean, svar;
    int tid = threadIdx.x, w = tid >> 5, l = tid & 31;

    if (tid < 32) ((float4*)xs)[tid] = ((const float4*)(g_x1 + tk*DE))[tid];
    __syncthreads();
    float4 xr = ((const float4*)xs)[l];

    for (int i = 0; i < ENCFF/8; ++i) {
        int j = w*(ENCFF/8) + i;
        float4 a = ((const float4*)(l1w + (size_t)j*DE))[l];
        float dot = warpSum(a.x*xr.x + a.y*xr.y + a.z*xr.z + a.w*xr.w);
        if (l == 0) hs[j] = fmaxf(dot + l1b[j], 0.f);
    }
    __syncthreads();

    {
        int o = tid & 127, half = tid >> 7;
        const float4* wr4 = (const float4*)(l2w + (size_t)o*ENCFF + half*(ENCFF/2));
        const float4* hs4 = (const float4*)(hs + half*(ENCFF/2));
        float acc = 0.f;
#pragma unroll 4
        for (int j = 0; j < ENCFF/8; ++j) {
            float4 a = wr4[j], bq = hs4[j];
            acc += a.x*bq.x + a.y*bq.y + a.z*bq.z + a.w*bq.w;
        }
        part[half][o] = acc;
    }
    __syncthreads();
    if (tid < DE) es[tid] = part[0][tid] + part[1][tid] + l2b[tid] + xs[tid];
    __syncthreads();

    float val = (tid < DE) ? es[tid] : 0.f;
    float sr2 = warpSum(val);
    if (l == 0 && w < 4) red[w] = sr2;
    __syncthreads();
    if (tid == 0) smean = (red[0]+red[1]+red[2]+red[3]) * (1.f/DE);
    __syncthreads();
    float dv = (tid < DE) ? (es[tid]-smean) : 0.f;
    float s2 = warpSum(dv*dv);
    if (l == 0 && w < 4) red[w] = s2;
    __syncthreads();
    if (tid == 0) svar = (red[0]+red[1]+red[2]+red[3]) * (1.f/DE);
    __syncthreads();
    if (tid < DE) es[tid] = (es[tid]-smean)*rsqrtf(svar+1e-5f)*g2[tid] + b2[tid];
    __syncthreads();

    float4 er = ((const float4*)es)[l];
    for (int i = 0; i < DM/8; ++i) {
        int o = w*(DM/8) + i;
        float4 a = ((const float4*)(vw + (size_t)o*(DM+DE) + DM))[l];
        float dot = warpSum(a.x*er.x + a.y*er.y + a.z*er.z + a.w*er.w);
        if (l == 0) g_Ve[tk*DM + o] = dot;
    }
}

// ---------------------------------------------------------------------------
// Launch 4 (PROFILED): merged enc_ff (blocks [0,32)) + main_attn ([32,2080)).
// launch_bounds(256,2): with __sincosf the body's live-state fits 128 regs,
// so 2 CTAs/SM should come without spills (watch DRAM% for the failure mode).
// ---------------------------------------------------------------------------
__global__ __launch_bounds__(256, 2) void main_attn_kernel(
        const float* __restrict__ R, const float* __restrict__ t,
        const float* __restrict__ mu, const float* __restrict__ Sigma,
        const float* __restrict__ l1w, const float* __restrict__ l1b,
        const float* __restrict__ l2w, const float* __restrict__ l2b,
        const float* __restrict__ g2,  const float* __restrict__ b2,
        const float* __restrict__ vw) {
    if (blockIdx.x < FFBLK) {
        enc_ff_body(blockIdx.x, l1w, l1b, l2w, l2b, g2, b2, vw);
        return;
    }
    extern __shared__ float feat[];            // [KE][768]
    __shared__ float sR[9], sT[3];
    __shared__ float sr[KE][3];
    __shared__ float sC9[KE][9];
    __shared__ float sfreq[NFREQ];

    int row = blockIdx.x - FFBLK;
    int b = row >> 10;
    int tid = threadIdx.x, w = tid >> 5, l = tid & 31;

    if (tid < 9)  sR[tid] = R[(size_t)row*9 + tid];
    if (tid >= 16 && tid < 19) sT[tid-16] = t[(size_t)row*3 + (tid-16)];
    if (tid >= 128 && tid < 256) sfreq[tid-128] = exp2f(7.0f*(float)(tid-128)/127.0f);
    __syncthreads();

    if (tid < KE) {
        int k = tid;
        float d0 = mu[(b*KE+k)*3+0] - sT[0];
        float d1 = mu[(b*KE+k)*3+1] - sT[1];
        float d2 = mu[(b*KE+k)*3+2] - sT[2];
#pragma unroll
        for (int i = 0; i < 3; ++i)
            sr[k][i] = sR[0*3+i]*d0 + sR[1*3+i]*d1 + sR[2*3+i]*d2;
        float Sg[9];
#pragma unroll
        for (int jj = 0; jj < 9; ++jj) Sg[jj] = Sigma[(b*KE+k)*9 + jj];
        float M1[9];
#pragma unroll
        for (int j = 0; j < 3; ++j)
#pragma unroll
            for (int m = 0; m < 3; ++m)
                M1[j*3+m] = Sg[j*3+0]*sR[0*3+m] + Sg[j*3+1]*sR[1*3+m] + Sg[j*3+2]*sR[2*3+m];
#pragma unroll
        for (int i = 0; i < 3; ++i)
#pragma unroll
            for (int m = 0; m < 3; ++m)
                sC9[k][i*3+m] = sR[0*3+i]*M1[0*3+m] + sR[1*3+i]*M1[1*3+m] + sR[2*3+i]*M1[2*3+m];
    }
    __syncthreads();

    for (int idx = tid; idx < KE*384; idx += 256) {
        int k = idx / 384;
        int jj = idx - k*384;
        int c = jj >> 7, f = jj & 127;
        float sv, cv;
        __sincosf(sr[k][c]*sfreq[f], &sv, &cv);
        feat[k*DM + jj]       = sv;
        feat[k*DM + 384 + jj] = cv;
    }
    __syncthreads();

    int h = w;
    const float* ubase = g_u + ((size_t)row*NH + h)*UD;
    float4 ur4[6];
    const float4* up4 = (const float4*)ubase;
#pragma unroll
    for (int m = 0; m < 6; ++m) ur4[m] = up4[l + m*32];
    float qcr[9];
#pragma unroll
    for (int m = 0; m < 9; ++m) qcr[m] = ubase[DM + m];

    float sc[KE];
#pragma unroll
    for (int k = 0; k < KE; ++k) {
        const float4* fk4 = (const float4*)(feat + k*DM);
        float p = 0.f;
#pragma unroll
        for (int m = 0; m < 6; ++m) {
            float4 f = fk4[l + m*32];
            float4 u = ur4[m];
            p += u.x*f.x + u.y*f.y + u.z*f.z + u.w*f.w;
        }
        p = warpSum(p);
        float cv = 0.f;
#pragma unroll
        for (int mm = 0; mm < 9; ++mm) cv += qcr[mm]*sC9[k][mm];
        sc[k] = (p + cv) * 0.10206207262f;
    }
    float mx = sc[0];
#pragma unroll
    for (int k = 1; k < KE; ++k) mx = fmaxf(mx, sc[k]);
    float ssum = 0.f;
#pragma unroll
    for (int k = 0; k < KE; ++k) { sc[k] = __expf(sc[k]-mx); ssum += sc[k]; }
    float inv = 1.f/ssum;
#pragma unroll
    for (int k = 0; k < KE; ++k) sc[k] *= inv;

    if (l == 0) {
#pragma unroll
        for (int k = 0; k < KE; ++k)
            g_attn[(size_t)row*(NH*KE) + h*KE + k] = sc[k];
    }

    float4* gout4 = (float4*)(g_gacc + ((size_t)row*NH + h)*DM);
#pragma unroll
    for (int m = 0; m < 6; ++m) {
        float4 acc = make_float4(0.f, 0.f, 0.f, 0.f);
#pragma unroll
        for (int k = 0; k < KE; ++k) {
            const float4 f = ((const float4*)(feat + k*DM))[l + m*32];
            float a = sc[k];
            acc.x += a*f.x; acc.y += a*f.y; acc.z += a*f.z; acc.w += a*f.w;
        }
        gout4[l + m*32] = acc;
    }
}

// ---------------------------------------------------------------------------
extern "C" void kernel_launch(void* const* d_in, const int* in_sizes, int n_in,
                              void* d_out, int out_size) {
    const float* s     = (const float*)d_in[0];
    const float* Rm    = (const float*)d_in[1];
    const float* t     = (const float*)d_in[2];
    const float* ellip = (const float*)d_in[3];
    const float* mu    = (const float*)d_in[4];
    const float* Sigma = (const float*)d_in[5];
    int off = (in_sizes[6] == BATCH*KE) ? 1 : 0;
    const float* mix_w     = (const float*)d_in[6+off];
    const float* lin_cov_w = (const float*)d_in[7+off];
    const float* q_w       = (const float*)d_in[8+off];
    const float* k_w       = (const float*)d_in[9+off];
    const float* v_w       = (const float*)d_in[10+off];
    const float* o_w       = (const float*)d_in[11+off];
    const float* enc_in_w  = (const float*)d_in[12+off];
    const float* enc_in_b  = (const float*)d_in[13+off];
    const float* enc_out_w = (const float*)d_in[14+off];
    const float* enc_out_b = (const float*)d_in[15+off];
    const float* lin1_w    = (const float*)d_in[16+off];
    const float* lin1_b    = (const float*)d_in[17+off];
    const float* lin2_w    = (const float*)d_in[18+off];
    const float* lin2_b    = (const float*)d_in[19+off];
    const float* ln1_g     = (const float*)d_in[20+off];
    const float* ln1_b     = (const float*)d_in[21+off];
    const float* ln2_g     = (const float*)d_in[22+off];
    const float* ln2_b     = (const float*)d_in[23+off];
    float* out = (float*)d_out;

    float *pG, *pWv, *pVp;
    cudaGetSymbolAddress((void**)&pG,  g_gacc);
    cudaGetSymbolAddress((void**)&pWv, g_Wv);
    cudaGetSymbolAddress((void**)&pVp, g_Vp);

    cudaFuncSetAttribute(main_attn_kernel,
                         cudaFuncAttributeMaxDynamicSharedMemorySize, KE*DM*4);

    // 1: wc + Wkc + Wv + Q
    fused_prep<<<1104, 256, GEMM_SMEM_BYTES>>>(k_w, lin_cov_w, mix_w, s, q_w, v_w);
    // 2: u-GEMM + enc_qkv
    fused_u<<<1696, 256, GEMM_SMEM_BYTES>>>(ellip, enc_in_w, enc_in_b);
    // 3: encoder attention
    enc_attn_kernel<<<BATCH, 256>>>(ellip, enc_out_w, enc_out_b, ln1_g, ln1_b);
    // 4 (PROFILED): enc_ff (front) + main attention
    main_attn_kernel<<<ROWS + FFBLK, 256, KE*DM*4>>>(
        Rm, t, mu, Sigma, lin1_w, lin1_b, lin2_w, lin2_b, ln2_g, ln2_b, v_w);
    // 5: Vp_h = g_h @ Wv_h^T + Vec (epilogue)
    gemm_tf32<1,1><<<dim3(2,16,NH), 256, EPI_SMEM_BYTES>>>(
        pG, pWv, pVp, DHD, DM, NH*DM, DM, DM,
        (long)DM, (long)DHD*DM, (long)DHD);
    // 6: out = Vp @ o_w^T
    gemm_tf32<1,0><<<dim3(12,16,1), 256, GEMM_SMEM_BYTES>>>(
        pVp, o_w, out, DM, DM, DM, DM, DM, 0, 0, 0);
    (void)n_in; (void)out_size;
}

// round 13
// speedup vs baseline: 1.1050x; 1.1050x over previous
#include <cuda_runtime.h>
#include <math.h>
#include <stdint.h>
#include <mma.h>

using namespace nvcuda;

// ---------------------------------------------------------------------------
// InvariantCrossAttention — factorized; 5 launches.
//   Wkc = [ k_w[:, :768] @ mix_w  |  k_w[:,768:] @ lin_cov_w | 0pad ]  [768 x 832]
//   u'[row,h,:] = Q_h[row] @ Wkc_h       (cols 0..767 = u, 768..776 = qc)
//   scores[h,k] = ( feat[k].u + C9[k].qc ) / sqrt(96);  attn stored to gmem
//   g[row,h,:] = sum_k attn feat[k]
//   Vp_h = g_h @ Wv_h^T + (sum_k attn_k Ve[b,k,:])   (epilogue in GEMM)
//   out = Vp @ o_w^T
// R13: R11 main body (natural regalloc — occupancy caps are falsified) +
// launch compaction: enc_qkv into prep (L1), enc_attn into u (L2).
// ---------------------------------------------------------------------------

#define BATCH  2
#define NQ     1024
#define KE     16
#define DM     768
#define DE     128
#define NH     8
#define DHD    96
#define NFREQ  128
#define ENCFF  2048
#define ROWS   (BATCH*NQ)   // 2048
#define UD     832
#define FFBLK  (BATCH*KE)   // 32

static __device__ float g_encqkv[BATCH*KE*3*DE];
static __device__ float g_x1[BATCH*KE*DE];
static __device__ float g_Ve[BATCH*KE*DM];
static __device__ float g_Wkc[DM*UD];
static __device__ float g_Wv[DM*DM];
static __device__ float g_Q[ROWS*DM];
static __device__ float g_u[(size_t)ROWS*NH*UD];
static __device__ float g_gacc[(size_t)ROWS*NH*DM];
static __device__ float g_attn[ROWS*NH*KE];
static __device__ float g_Vp[ROWS*DM];

__device__ __forceinline__ float warpSum(float v) {
#pragma unroll
    for (int o = 16; o > 0; o >>= 1) v += __shfl_xor_sync(0xffffffffu, v, o);
    return v;
}

// ---------------------------------------------------------------------------
// TF32 GEMM body (single-buffered).  TB=0: C=A@B,  TB=1: C=A@B^T.
// EPI=1: writeback adds sum_k attn[m,k]*Ve[b,k,h*96+n]  (Vp GEMM only).
// Block tile 128x64, 8 warps of 32x32, wmma m16n16k8.
// ---------------------------------------------------------------------------
#define GEMM_SMEM_BYTES (8704*4)
#define EPI_SMEM_BYTES  ((8704+1024+2048)*4)
// fused_u needs max(GEMM smem, enc_attn smem = (KE*3*DE + 2*KE*DE) floats)
#define UATTN_SMEM_FLOATS (KE*3*DE + 2*KE*DE)   // 10240 floats = 40960 B
#define UATTN_SMEM_BYTES (UATTN_SMEM_FLOATS*4)

template<int TB, int EPI>
__device__ __forceinline__ void gemm_body(
        const float* __restrict__ A, const float* __restrict__ B,
        float* __restrict__ C,
        int Ndim, int Kdim, int lda, int ldb, int ldc,
        int m0, int n0, int h) {
    extern __shared__ float smem[];
    float* As = smem;               // [128][36]
    float* Bs = smem + 128*36;      // NN: [32][68] ; NT: [64][36]
    float* Cs = smem;               // [128][68] after mainloop

    int tid = threadIdx.x;
    int w = tid >> 5, wm = w >> 1, wn = w & 1;

    wmma::fragment<wmma::accumulator, 16, 16, 8, float> acc[2][2];
#pragma unroll
    for (int i = 0; i < 2; ++i)
#pragma unroll
        for (int j = 0; j < 2; ++j) wmma::fill_fragment(acc[i][j], 0.f);

    int ar = tid >> 3;
    int ac = (tid & 7) * 4;

    for (int k0 = 0; k0 < Kdim; k0 += 32) {
#pragma unroll
        for (int rr = 0; rr < 128; rr += 32) {
            float4 v = *(const float4*)&A[(size_t)(m0 + ar + rr)*lda + k0 + ac];
            v.x = wmma::__float_to_tf32(v.x); v.y = wmma::__float_to_tf32(v.y);
            v.z = wmma::__float_to_tf32(v.z); v.w = wmma::__float_to_tf32(v.w);
            *(float4*)&As[(ar + rr)*36 + ac] = v;
        }
        if (TB == 0) {
            int bk = tid >> 4;
            int bn = (tid & 15) * 4;
#pragma unroll
            for (int kk = 0; kk < 32; kk += 16) {
                float4 v = *(const float4*)&B[(size_t)(k0 + bk + kk)*ldb + n0 + bn];
                v.x = wmma::__float_to_tf32(v.x); v.y = wmma::__float_to_tf32(v.y);
                v.z = wmma::__float_to_tf32(v.z); v.w = wmma::__float_to_tf32(v.w);
                *(float4*)&Bs[(bk + kk)*68 + bn] = v;
            }
        } else {
            int bn = tid >> 3;
            int bc = (tid & 7) * 4;
#pragma unroll
            for (int nn = 0; nn < 64; nn += 32) {
                int n = n0 + bn + nn;
                float4 v = make_float4(0.f, 0.f, 0.f, 0.f);
                if (n < Ndim) {
                    v = *(const float4*)&B[(size_t)n*ldb + k0 + bc];
                    v.x = wmma::__float_to_tf32(v.x); v.y = wmma::__float_to_tf32(v.y);
                    v.z = wmma::__float_to_tf32(v.z); v.w = wmma::__float_to_tf32(v.w);
                }
                *(float4*)&Bs[(bn + nn)*36 + bc] = v;
            }
        }
        __syncthreads();

#pragma unroll
        for (int ks = 0; ks < 4; ++ks) {
            wmma::fragment<wmma::matrix_a, 16, 16, 8, wmma::precision::tf32, wmma::row_major> af[2];
#pragma unroll
            for (int i = 0; i < 2; ++i)
                wmma::load_matrix_sync(af[i], &As[(wm*32 + i*16)*36 + ks*8], 36);
            if (TB == 0) {
                wmma::fragment<wmma::matrix_b, 16, 16, 8, wmma::precision::tf32, wmma::row_major> bf[2];
#pragma unroll
                for (int j = 0; j < 2; ++j)
                    wmma::load_matrix_sync(bf[j], &Bs[(ks*8)*68 + wn*32 + j*16], 68);
#pragma unroll
                for (int i = 0; i < 2; ++i)
#pragma unroll
                    for (int j = 0; j < 2; ++j)
                        wmma::mma_sync(acc[i][j], af[i], bf[j], acc[i][j]);
            } else {
                wmma::fragment<wmma::matrix_b, 16, 16, 8, wmma::precision::tf32, wmma::col_major> bf[2];
#pragma unroll
                for (int j = 0; j < 2; ++j)
                    wmma::load_matrix_sync(bf[j], &Bs[(wn*32 + j*16)*36 + ks*8], 36);
#pragma unroll
                for (int i = 0; i < 2; ++i)
#pragma unroll
                    for (int j = 0; j < 2; ++j)
                        wmma::mma_sync(acc[i][j], af[i], bf[j], acc[i][j]);
            }
        }
        __syncthreads();
    }

#pragma unroll
    for (int i = 0; i < 2; ++i)
#pragma unroll
        for (int j = 0; j < 2; ++j)
            wmma::store_matrix_sync(&Cs[(wm*32 + i*16)*68 + wn*32 + j*16],
                                    acc[i][j], 68, wmma::mem_row_major);
    __syncthreads();

    if (EPI) {
        float* sVe = smem + 8704;         // [16][64]
        float* sAt = smem + 8704 + 1024;  // [128][16]
        int b = m0 >> 10;
        for (int idx = tid; idx < KE*64; idx += 256) {
            int k = idx >> 6, n = idx & 63;
            int gn = n0 + n;
            sVe[idx] = (gn < Ndim) ? g_Ve[(size_t)(b*KE + k)*DM + h*DHD + gn] : 0.f;
        }
        for (int idx = tid; idx < 128*KE; idx += 256) {
            int m = idx >> 4, k = idx & 15;
            sAt[idx] = g_attn[(size_t)(m0 + m)*(NH*KE) + h*KE + k];
        }
        __syncthreads();
        for (int idx = tid; idx < 128*64; idx += 256) {
            int m = idx >> 6, n = idx & 63;
            int gn = n0 + n;
            if (gn < Ndim) {
                float v = Cs[m*68 + n];
#pragma unroll
                for (int k = 0; k < KE; ++k) v += sAt[m*16 + k]*sVe[k*64 + n];
                C[(size_t)(m0 + m)*ldc + gn] = v;
            }
        }
    } else {
        for (int idx = tid; idx < 128*64; idx += 256) {
            int m = idx >> 6, n = idx & 63;
            int gn = n0 + n;
            if (gn < Ndim)
                C[(size_t)(m0 + m)*ldc + gn] = Cs[m*68 + n];
        }
    }
}

template<int TB, int EPI>
__global__ __launch_bounds__(256) void gemm_tf32(
        const float* __restrict__ A, const float* __restrict__ B,
        float* __restrict__ C,
        int Ndim, int Kdim, int lda, int ldb, int ldc,
        long aZ, long bZ, long cZ) {
    gemm_body<TB, EPI>(A + (long)blockIdx.z*aZ, B + (long)blockIdx.z*bZ,
                       C + (long)blockIdx.z*cZ,
                       Ndim, Kdim, lda, ldb, ldc,
                       blockIdx.y*128, blockIdx.x*64, blockIdx.z);
}

// ---------------------------------------------------------------------------
// Launch 1: fused prep — [0,768) wc, [768,840) Wkc, [840,912) Wv,
// [912,1104) Q-GEMM, [1104,1136) enc_qkv (inputs-only dependency).
// ---------------------------------------------------------------------------
__global__ __launch_bounds__(256) void fused_prep(
        const float* __restrict__ kw, const float* __restrict__ lcw,
        const float* __restrict__ mixw, const float* __restrict__ s,
        const float* __restrict__ qw, const float* __restrict__ vw,
        const float* __restrict__ ellip, const float* __restrict__ eiw,
        const float* __restrict__ eib) {
    int bx = blockIdx.x;
    if (bx < 768) {
        int o = bx;
        int wg = threadIdx.x >> 5, l = threadIdx.x & 31;
        for (int m = wg; m < 9; m += 8) {
            float acc = 0.f;
            for (int j = l; j < DM; j += 32)
                acc += kw[(size_t)o*(2*DM) + DM + j]*lcw[j*9 + m];
            acc = warpSum(acc);
            if (l == 0) g_Wkc[(size_t)o*UD + DM + m] = acc;
        }
    } else if (bx < 840) {
        int idx = bx - 768;
        gemm_body<0,0>(kw, mixw, g_Wkc, DM, DM, 2*DM, DM, UD,
                       (idx/12)*128, (idx%12)*64, 0);
    } else if (bx < 912) {
        int idx = bx - 840;
        gemm_body<0,0>(vw, mixw, g_Wv, DM, DM, DM+DE, DM, DM,
                       (idx/12)*128, (idx%12)*64, 0);
    } else if (bx < 1104) {
        int idx = bx - 912;
        gemm_body<1,0>(s, qw, g_Q, DM, DM, DM, DM, DM,
                       (idx/12)*128, (idx%12)*64, 0);
    } else {
        // enc_qkv: one token per block, warp-per-output
        extern __shared__ float smemq[];
        float* xs = smemq;   // [DE]
        int tk = bx - 1104;
        int tid = threadIdx.x, w = tid >> 5, l = tid & 31;
        if (tid < 32) ((float4*)xs)[tid] = ((const float4*)(ellip + tk*DE))[tid];
        __syncthreads();
        float4 xr = ((const float4*)xs)[l];
        for (int i = 0; i < 48; ++i) {
            int o = w*48 + i;
            float4 a = ((const float4*)(eiw + (size_t)o*DE))[l];
            float dot = warpSum(a.x*xr.x + a.y*xr.y + a.z*xr.z + a.w*xr.w);
            if (l == 0) g_encqkv[tk*3*DE + o] = dot + eib[o];
        }
    }
}

// ---------------------------------------------------------------------------
// enc_attn body (blocks 1664..1665 of launch 2) — uses dynamic smem.
// ---------------------------------------------------------------------------
__device__ void enc_attn_body(
        int b,
        const float* __restrict__ xin, const float* __restrict__ eow,
        const float* __restrict__ eob, const float* __restrict__ g1,
        const float* __restrict__ b1) {
    extern __shared__ float smema[];
    float (*qkv)[3*DE] = (float(*)[3*DE])smema;            // [KE][3*DE]
    float (*ao)[DE]    = (float(*)[DE])(smema + KE*3*DE);  // [KE][DE]
    float (*y)[DE]     = (float(*)[DE])(smema + KE*3*DE + KE*DE); // [KE][DE]
    int tid = threadIdx.x, w = tid >> 5, l = tid & 31;

    for (int idx = tid; idx < KE*3*DE; idx += 256)
        qkv[idx/(3*DE)][idx%(3*DE)] = g_encqkv[b*KE*3*DE + idx];
    __syncthreads();

#pragma unroll
    for (int pi = 0; pi < 8; ++pi) {
        int p = w*8 + pi;
        int h = p >> 4, q = p & 15;
        float qv = qkv[q][h*32 + l];
        float sc[KE];
#pragma unroll
        for (int k = 0; k < KE; ++k) {
            float pr = qv * qkv[k][DE + h*32 + l];
            sc[k] = warpSum(pr) * 0.17677669529f;
        }
        float mx = sc[0];
#pragma unroll
        for (int k = 1; k < KE; ++k) mx = fmaxf(mx, sc[k]);
        float ssum = 0.f;
#pragma unroll
        for (int k = 0; k < KE; ++k) { sc[k] = __expf(sc[k]-mx); ssum += sc[k]; }
        float inv = 1.f/ssum;
        float acc = 0.f;
#pragma unroll
        for (int k = 0; k < KE; ++k) acc += sc[k]*inv * qkv[k][2*DE + h*32 + l];
        ao[q][h*32 + l] = acc;
    }
    __syncthreads();

    for (int i = 0; i < 256; ++i) {
        int j = w*256 + i;
        int q = j >> 7, o = j & 127;
        float4 a = ((const float4*)(eow + (size_t)o*DE))[l];
        float4 x4 = ((const float4*)&ao[q][0])[l];
        float dot = warpSum(a.x*x4.x + a.y*x4.y + a.z*x4.z + a.w*x4.w);
        if (l == 0) y[q][o] = dot + eob[o] + xin[(b*KE + q)*DE + o];
    }
    __syncthreads();

#pragma unroll
    for (int qi = 0; qi < 2; ++qi) {
        int q = w*2 + qi;
        float v0 = y[q][l], v1 = y[q][l+32], v2 = y[q][l+64], v3 = y[q][l+96];
        float mean = warpSum(v0+v1+v2+v3) * (1.f/DE);
        float d0 = v0-mean, d1 = v1-mean, d2 = v2-mean, d3 = v3-mean;
        float var = warpSum(d0*d0+d1*d1+d2*d2+d3*d3) * (1.f/DE);
        float inv = rsqrtf(var + 1e-5f);
        g_x1[(b*KE+q)*DE + l]    = d0*inv*g1[l]    + b1[l];
        g_x1[(b*KE+q)*DE + l+32] = d1*inv*g1[l+32] + b1[l+32];
        g_x1[(b*KE+q)*DE + l+64] = d2*inv*g1[l+64] + b1[l+64];
        g_x1[(b*KE+q)*DE + l+96] = d3*inv*g1[l+96] + b1[l+96];
    }
}

// ---------------------------------------------------------------------------
// Launch 2: fused u-GEMM ([0,1664)) + enc_attn ([1664,1666))
// ---------------------------------------------------------------------------
__global__ __launch_bounds__(256) void fused_u(
        const float* __restrict__ xin, const float* __restrict__ eow,
        const float* __restrict__ eob, const float* __restrict__ g1,
        const float* __restrict__ b1) {
    int bx = blockIdx.x;
    if (bx < 1664) {
        int z = bx / 208, rem = bx % 208;
        gemm_body<0,0>(g_Q + z*DHD, g_Wkc + (size_t)z*DHD*UD, g_u + z*UD,
                       UD, DHD, DM, UD, NH*UD, (rem/13)*128, (rem%13)*64, z);
    } else {
        enc_attn_body(bx - 1664, xin, eow, eob, g1, b1);
    }
}

// ---------------------------------------------------------------------------
// enc_ff body (blocks 0..31 of merged launch 3)
// ---------------------------------------------------------------------------
__device__ void enc_ff_body(
        int tk,
        const float* __restrict__ l1w, const float* __restrict__ l1b,
        const float* __restrict__ l2w, const float* __restrict__ l2b,
        const float* __restrict__ g2,  const float* __restrict__ b2,
        const float* __restrict__ vw) {
    __shared__ float xs[DE];
    __shared__ float hs[ENCFF];
    __shared__ float es[DE];
    __shared__ float part[2][DE];
    __shared__ float red[8];
    __shared__ float smean, svar;
    int tid = threadIdx.x, w = tid >> 5, l = tid & 31;

    if (tid < 32) ((float4*)xs)[tid] = ((const float4*)(g_x1 + tk*DE))[tid];
    __syncthreads();
    float4 xr = ((const float4*)xs)[l];

    for (int i = 0; i < ENCFF/8; ++i) {
        int j = w*(ENCFF/8) + i;
        float4 a = ((const float4*)(l1w + (size_t)j*DE))[l];
        float dot = warpSum(a.x*xr.x + a.y*xr.y + a.z*xr.z + a.w*xr.w);
        if (l == 0) hs[j] = fmaxf(dot + l1b[j], 0.f);
    }
    __syncthreads();

    {
        int o = tid & 127, half = tid >> 7;
        const float4* wr4 = (const float4*)(l2w + (size_t)o*ENCFF + half*(ENCFF/2));
        const float4* hs4 = (const float4*)(hs + half*(ENCFF/2));
        float acc = 0.f;
#pragma unroll 4
        for (int j = 0; j < ENCFF/8; ++j) {
            float4 a = wr4[j], bq = hs4[j];
            acc += a.x*bq.x + a.y*bq.y + a.z*bq.z + a.w*bq.w;
        }
        part[half][o] = acc;
    }
    __syncthreads();
    if (tid < DE) es[tid] = part[0][tid] + part[1][tid] + l2b[tid] + xs[tid];
    __syncthreads();

    float val = (tid < DE) ? es[tid] : 0.f;
    float sr2 = warpSum(val);
    if (l == 0 && w < 4) red[w] = sr2;
    __syncthreads();
    if (tid == 0) smean = (red[0]+red[1]+red[2]+red[3]) * (1.f/DE);
    __syncthreads();
    float dv = (tid < DE) ? (es[tid]-smean) : 0.f;
    float s2 = warpSum(dv*dv);
    if (l == 0 && w < 4) red[w] = s2;
    __syncthreads();
    if (tid == 0) svar = (red[0]+red[1]+red[2]+red[3]) * (1.f/DE);
    __syncthreads();
    if (tid < DE) es[tid] = (es[tid]-smean)*rsqrtf(svar+1e-5f)*g2[tid] + b2[tid];
    __syncthreads();

    float4 er = ((const float4*)es)[l];
    for (int i = 0; i < DM/8; ++i) {
        int o = w*(DM/8) + i;
        float4 a = ((const float4*)(vw + (size_t)o*(DM+DE) + DM))[l];
        float dot = warpSum(a.x*er.x + a.y*er.y + a.z*er.z + a.w*er.w);
        if (l == 0) g_Ve[tk*DM + o] = dot;
    }
}

// ---------------------------------------------------------------------------
// Launch 3 (PROFILED): merged enc_ff (blocks [0,32)) + main_attn ([32,2080)).
// Natural regalloc (no cap — R7/R8/R12 falsified caps), ff at grid front.
// ---------------------------------------------------------------------------
__global__ __launch_bounds__(256) void main_attn_kernel(
        const float* __restrict__ R, const float* __restrict__ t,
        const float* __restrict__ mu, const float* __restrict__ Sigma,
        const float* __restrict__ l1w, const float* __restrict__ l1b,
        const float* __restrict__ l2w, const float* __restrict__ l2b,
        const float* __restrict__ g2,  const float* __restrict__ b2,
        const float* __restrict__ vw) {
    if (blockIdx.x < FFBLK) {
        enc_ff_body(blockIdx.x, l1w, l1b, l2w, l2b, g2, b2, vw);
        return;
    }
    extern __shared__ float feat[];            // [KE][768]
    __shared__ float sR[9], sT[3];
    __shared__ float sr[KE][3];
    __shared__ float sC9[KE][9];
    __shared__ float sfreq[NFREQ];

    int row = blockIdx.x - FFBLK;
    int b = row >> 10;
    int tid = threadIdx.x, w = tid >> 5, l = tid & 31;

    if (tid < 9)  sR[tid] = R[(size_t)row*9 + tid];
    if (tid >= 16 && tid < 19) sT[tid-16] = t[(size_t)row*3 + (tid-16)];
    if (tid >= 128 && tid < 256) sfreq[tid-128] = exp2f(7.0f*(float)(tid-128)/127.0f);
    __syncthreads();

    if (tid < KE) {
        int k = tid;
        float d0 = mu[(b*KE+k)*3+0] - sT[0];
        float d1 = mu[(b*KE+k)*3+1] - sT[1];
        float d2 = mu[(b*KE+k)*3+2] - sT[2];
#pragma unroll
        for (int i = 0; i < 3; ++i)
            sr[k][i] = sR[0*3+i]*d0 + sR[1*3+i]*d1 + sR[2*3+i]*d2;
        float Sg[9];
#pragma unroll
        for (int jj = 0; jj < 9; ++jj) Sg[jj] = Sigma[(b*KE+k)*9 + jj];
        float M1[9];
#pragma unroll
        for (int j = 0; j < 3; ++j)
#pragma unroll
            for (int m = 0; m < 3; ++m)
                M1[j*3+m] = Sg[j*3+0]*sR[0*3+m] + Sg[j*3+1]*sR[1*3+m] + Sg[j*3+2]*sR[2*3+m];
#pragma unroll
        for (int i = 0; i < 3; ++i)
#pragma unroll
            for (int m = 0; m < 3; ++m)
                sC9[k][i*3+m] = sR[0*3+i]*M1[0*3+m] + sR[1*3+i]*M1[1*3+m] + sR[2*3+i]*M1[2*3+m];
    }
    __syncthreads();

    for (int idx = tid; idx < KE*384; idx += 256) {
        int k = idx / 384;
        int jj = idx - k*384;
        int c = jj >> 7, f = jj & 127;
        float sv, cv;
        __sincosf(sr[k][c]*sfreq[f], &sv, &cv);
        feat[k*DM + jj]       = sv;
        feat[k*DM + 384 + jj] = cv;
    }
    __syncthreads();

    int h = w;
    const float* ubase = g_u + ((size_t)row*NH + h)*UD;
    float4 ur4[6];
    const float4* up4 = (const float4*)ubase;
#pragma unroll
    for (int m = 0; m < 6; ++m) ur4[m] = up4[l + m*32];
    float qcr[9];
#pragma unroll
    for (int m = 0; m < 9; ++m) qcr[m] = ubase[DM + m];

    float sc[KE];
#pragma unroll
    for (int k = 0; k < KE; ++k) {
        const float4* fk4 = (const float4*)(feat + k*DM);
        float p = 0.f;
#pragma unroll
        for (int m = 0; m < 6; ++m) {
            float4 f = fk4[l + m*32];
            float4 u = ur4[m];
            p += u.x*f.x + u.y*f.y + u.z*f.z + u.w*f.w;
        }
        p = warpSum(p);
        float cv = 0.f;
#pragma unroll
        for (int mm = 0; mm < 9; ++mm) cv += qcr[mm]*sC9[k][mm];
        sc[k] = (p + cv) * 0.10206207262f;
    }
    float mx = sc[0];
#pragma unroll
    for (int k = 1; k < KE; ++k) mx = fmaxf(mx, sc[k]);
    float ssum = 0.f;
#pragma unroll
    for (int k = 0; k < KE; ++k) { sc[k] = __expf(sc[k]-mx); ssum += sc[k]; }
    float inv = 1.f/ssum;
#pragma unroll
    for (int k = 0; k < KE; ++k) sc[k] *= inv;

    if (l == 0) {
#pragma unroll
        for (int k = 0; k < KE; ++k)
            g_attn[(size_t)row*(NH*KE) + h*KE + k] = sc[k];
    }

    float4* gout4 = (float4*)(g_gacc + ((size_t)row*NH + h)*DM);
#pragma unroll
    for (int m = 0; m < 6; ++m) {
        float4 acc = make_float4(0.f, 0.f, 0.f, 0.f);
#pragma unroll
        for (int k = 0; k < KE; ++k) {
            const float4 f = ((const float4*)(feat + k*DM))[l + m*32];
            float a = sc[k];
            acc.x += a*f.x; acc.y += a*f.y; acc.z += a*f.z; acc.w += a*f.w;
        }
        gout4[l + m*32] = acc;
    }
}

// ---------------------------------------------------------------------------
extern "C" void kernel_launch(void* const* d_in, const int* in_sizes, int n_in,
                              void* d_out, int out_size) {
    const float* s     = (const float*)d_in[0];
    const float* Rm    = (const float*)d_in[1];
    const float* t     = (const float*)d_in[2];
    const float* ellip = (const float*)d_in[3];
    const float* mu    = (const float*)d_in[4];
    const float* Sigma = (const float*)d_in[5];
    int off = (in_sizes[6] == BATCH*KE) ? 1 : 0;
    const float* mix_w     = (const float*)d_in[6+off];
    const float* lin_cov_w = (const float*)d_in[7+off];
    const float* q_w       = (const float*)d_in[8+off];
    const float* k_w       = (const float*)d_in[9+off];
    const float* v_w       = (const float*)d_in[10+off];
    const float* o_w       = (const float*)d_in[11+off];
    const float* enc_in_w  = (const float*)d_in[12+off];
    const float* enc_in_b  = (const float*)d_in[13+off];
    const float* enc_out_w = (const float*)d_in[14+off];
    const float* enc_out_b = (const float*)d_in[15+off];
    const float* lin1_w    = (const float*)d_in[16+off];
    const float* lin1_b    = (const float*)d_in[17+off];
    const float* lin2_w    = (const float*)d_in[18+off];
    const float* lin2_b    = (const float*)d_in[19+off];
    const float* ln1_g     = (const float*)d_in[20+off];
    const float* ln1_b     = (const float*)d_in[21+off];
    const float* ln2_g     = (const float*)d_in[22+off];
    const float* ln2_b     = (const float*)d_in[23+off];
    float* out = (float*)d_out;

    float *pG, *pWv, *pVp;
    cudaGetSymbolAddress((void**)&pG,  g_gacc);
    cudaGetSymbolAddress((void**)&pWv, g_Wv);
    cudaGetSymbolAddress((void**)&pVp, g_Vp);

    cudaFuncSetAttribute(main_attn_kernel,
                         cudaFuncAttributeMaxDynamicSharedMemorySize, KE*DM*4);

    // 1: wc + Wkc + Wv + Q + enc_qkv
    fused_prep<<<1136, 256, GEMM_SMEM_BYTES>>>(
        k_w, lin_cov_w, mix_w, s, q_w, v_w, ellip, enc_in_w, enc_in_b);
    // 2: u-GEMM + enc_attn  (dyn smem sized for enc_attn's 40KB)
    fused_u<<<1666, 256, UATTN_SMEM_BYTES>>>(
        ellip, enc_out_w, enc_out_b, ln1_g, ln1_b);
    // 3 (PROFILED): enc_ff (front) + main attention
    main_attn_kernel<<<ROWS + FFBLK, 256, KE*DM*4>>>(
        Rm, t, mu, Sigma, lin1_w, lin1_b, lin2_w, lin2_b, ln2_g, ln2_b, v_w);
    // 4: Vp_h = g_h @ Wv_h^T + Vec (epilogue)
    gemm_tf32<1,1><<<dim3(2,16,NH), 256, EPI_SMEM_BYTES>>>(
        pG, pWv, pVp, DHD, DM, NH*DM, DM, DM,
        (long)DM, (long)DHD*DM, (long)DHD);
    // 5: out = Vp @ o_w^T
    gemm_tf32<1,0><<<dim3(12,16,1), 256, GEMM_SMEM_BYTES>>>(
        pVp, o_w, out, DM, DM, DM, DM, DM, 0, 0, 0);
    (void)n_in; (void)out_size;
}

// round 14
// speedup vs baseline: 1.1346x; 1.0268x over previous
#include <cuda_runtime.h>
#include <cuda_fp16.h>
#include <math.h>
#include <stdint.h>
#include <mma.h>

using namespace nvcuda;

// ---------------------------------------------------------------------------
// InvariantCrossAttention — factorized; 5 launches.
//   Wkc = [ k_w[:, :768] @ mix_w  |  k_w[:,768:] @ lin_cov_w | 0pad ]  [768 x 832]
//   u'[row,h,:] = Q_h[row] @ Wkc_h       (cols 0..767 = u, 768..776 = qc)
//   scores[h,k] = ( feat[k].u + C9[k].qc ) / sqrt(96);  attn stored to gmem
//   g[row,h,:] = sum_k attn feat[k]      (stored FP16 — values in [-1,1],
//                                         10-bit mantissa == tf32's)
//   Vp_h = g_h @ Wv_h^T + (sum_k attn_k Ve[b,k,:])   (epilogue in GEMM)
//   out = Vp @ o_w^T
// R14: g tensor in fp16 — halves main_attn's write traffic and the Vp GEMM's
// A-read traffic (both latency/BW-bound).  u stays fp32 (score-path margin).
// ---------------------------------------------------------------------------

#define BATCH  2
#define NQ     1024
#define KE     16
#define DM     768
#define DE     128
#define NH     8
#define DHD    96
#define NFREQ  128
#define ENCFF  2048
#define ROWS   (BATCH*NQ)   // 2048
#define UD     832
#define FFBLK  (BATCH*KE)   // 32

static __device__ float  g_encqkv[BATCH*KE*3*DE];
static __device__ float  g_x1[BATCH*KE*DE];
static __device__ float  g_Ve[BATCH*KE*DM];
static __device__ float  g_Wkc[DM*UD];
static __device__ float  g_Wv[DM*DM];
static __device__ float  g_Q[ROWS*DM];
static __device__ float  g_u[(size_t)ROWS*NH*UD];
static __device__ __half g_gacc[(size_t)ROWS*NH*DM];
static __device__ float  g_attn[ROWS*NH*KE];
static __device__ float  g_Vp[ROWS*DM];

__device__ __forceinline__ float warpSum(float v) {
#pragma unroll
    for (int o = 16; o > 0; o >>= 1) v += __shfl_xor_sync(0xffffffffu, v, o);
    return v;
}

// ---------------------------------------------------------------------------
// TF32 GEMM body (single-buffered).  TB=0: C=A@B,  TB=1: C=A@B^T.
// EPI=1: writeback adds sum_k attn[m,k]*Ve[b,k,h*96+n]  (Vp GEMM only).
// HIN=1: A matrix is fp16 (element strides in halfs; fp16->f32 is exact).
// Block tile 128x64, 8 warps of 32x32, wmma m16n16k8.
// ---------------------------------------------------------------------------
#define GEMM_SMEM_BYTES (8704*4)
#define EPI_SMEM_BYTES  ((8704+1024+2048)*4)
#define UATTN_SMEM_FLOATS (KE*3*DE + 2*KE*DE)
#define UATTN_SMEM_BYTES (UATTN_SMEM_FLOATS*4)

template<int TB, int EPI, int HIN>
__device__ __forceinline__ void gemm_body(
        const float* __restrict__ A, const float* __restrict__ B,
        float* __restrict__ C,
        int Ndim, int Kdim, int lda, int ldb, int ldc,
        int m0, int n0, int h) {
    extern __shared__ float smem[];
    float* As = smem;               // [128][36]
    float* Bs = smem + 128*36;      // NN: [32][68] ; NT: [64][36]
    float* Cs = smem;               // [128][68] after mainloop

    int tid = threadIdx.x;
    int w = tid >> 5, wm = w >> 1, wn = w & 1;

    wmma::fragment<wmma::accumulator, 16, 16, 8, float> acc[2][2];
#pragma unroll
    for (int i = 0; i < 2; ++i)
#pragma unroll
        for (int j = 0; j < 2; ++j) wmma::fill_fragment(acc[i][j], 0.f);

    int ar = tid >> 3;
    int ac = (tid & 7) * 4;

    for (int k0 = 0; k0 < Kdim; k0 += 32) {
        if (HIN) {
            // A fp16: 128 rows x 32 halfs = 512 x (8-half/16B) loads
            const __half* Ah = (const __half*)A;
#pragma unroll
            for (int i = 0; i < 2; ++i) {
                int idx = tid + 256*i;          // 0..511
                int row = idx >> 2, seg = idx & 3;
                float4 raw = *(const float4*)&Ah[(size_t)(m0 + row)*lda + k0 + seg*8];
                const __half2* hp = (const __half2*)&raw;
                float2 f0 = __half22float2(hp[0]);
                float2 f1 = __half22float2(hp[1]);
                float2 f2 = __half22float2(hp[2]);
                float2 f3 = __half22float2(hp[3]);
                float* dst = &As[row*36 + seg*8];
                dst[0]=f0.x; dst[1]=f0.y; dst[2]=f1.x; dst[3]=f1.y;
                dst[4]=f2.x; dst[5]=f2.y; dst[6]=f3.x; dst[7]=f3.y;
            }
        } else {
#pragma unroll
            for (int rr = 0; rr < 128; rr += 32) {
                float4 v = *(const float4*)&A[(size_t)(m0 + ar + rr)*lda + k0 + ac];
                v.x = wmma::__float_to_tf32(v.x); v.y = wmma::__float_to_tf32(v.y);
                v.z = wmma::__float_to_tf32(v.z); v.w = wmma::__float_to_tf32(v.w);
                *(float4*)&As[(ar + rr)*36 + ac] = v;
            }
        }
        if (TB == 0) {
            int bk = tid >> 4;
            int bn = (tid & 15) * 4;
#pragma unroll
            for (int kk = 0; kk < 32; kk += 16) {
                float4 v = *(const float4*)&B[(size_t)(k0 + bk + kk)*ldb + n0 + bn];
                v.x = wmma::__float_to_tf32(v.x); v.y = wmma::__float_to_tf32(v.y);
                v.z = wmma::__float_to_tf32(v.z); v.w = wmma::__float_to_tf32(v.w);
                *(float4*)&Bs[(bk + kk)*68 + bn] = v;
            }
        } else {
            int bn = tid >> 3;
            int bc = (tid & 7) * 4;
#pragma unroll
            for (int nn = 0; nn < 64; nn += 32) {
                int n = n0 + bn + nn;
                float4 v = make_float4(0.f, 0.f, 0.f, 0.f);
                if (n < Ndim) {
                    v = *(const float4*)&B[(size_t)n*ldb + k0 + bc];
                    v.x = wmma::__float_to_tf32(v.x); v.y = wmma::__float_to_tf32(v.y);
                    v.z = wmma::__float_to_tf32(v.z); v.w = wmma::__float_to_tf32(v.w);
                }
                *(float4*)&Bs[(bn + nn)*36 + bc] = v;
            }
        }
        __syncthreads();

#pragma unroll
        for (int ks = 0; ks < 4; ++ks) {
            wmma::fragment<wmma::matrix_a, 16, 16, 8, wmma::precision::tf32, wmma::row_major> af[2];
#pragma unroll
            for (int i = 0; i < 2; ++i)
                wmma::load_matrix_sync(af[i], &As[(wm*32 + i*16)*36 + ks*8], 36);
            if (TB == 0) {
                wmma::fragment<wmma::matrix_b, 16, 16, 8, wmma::precision::tf32, wmma::row_major> bf[2];
#pragma unroll
                for (int j = 0; j < 2; ++j)
                    wmma::load_matrix_sync(bf[j], &Bs[(ks*8)*68 + wn*32 + j*16], 68);
#pragma unroll
                for (int i = 0; i < 2; ++i)
#pragma unroll
                    for (int j = 0; j < 2; ++j)
                        wmma::mma_sync(acc[i][j], af[i], bf[j], acc[i][j]);
            } else {
                wmma::fragment<wmma::matrix_b, 16, 16, 8, wmma::precision::tf32, wmma::col_major> bf[2];
#pragma unroll
                for (int j = 0; j < 2; ++j)
                    wmma::load_matrix_sync(bf[j], &Bs[(wn*32 + j*16)*36 + ks*8], 36);
#pragma unroll
                for (int i = 0; i < 2; ++i)
#pragma unroll
                    for (int j = 0; j < 2; ++j)
                        wmma::mma_sync(acc[i][j], af[i], bf[j], acc[i][j]);
            }
        }
        __syncthreads();
    }

#pragma unroll
    for (int i = 0; i < 2; ++i)
#pragma unroll
        for (int j = 0; j < 2; ++j)
            wmma::store_matrix_sync(&Cs[(wm*32 + i*16)*68 + wn*32 + j*16],
                                    acc[i][j], 68, wmma::mem_row_major);
    __syncthreads();

    if (EPI) {
        float* sVe = smem + 8704;         // [16][64]
        float* sAt = smem + 8704 + 1024;  // [128][16]
        int b = m0 >> 10;
        for (int idx = tid; idx < KE*64; idx += 256) {
            int k = idx >> 6, n = idx & 63;
            int gn = n0 + n;
            sVe[idx] = (gn < Ndim) ? g_Ve[(size_t)(b*KE + k)*DM + h*DHD + gn] : 0.f;
        }
        for (int idx = tid; idx < 128*KE; idx += 256) {
            int m = idx >> 4, k = idx & 15;
            sAt[idx] = g_attn[(size_t)(m0 + m)*(NH*KE) + h*KE + k];
        }
        __syncthreads();
        for (int idx = tid; idx < 128*64; idx += 256) {
            int m = idx >> 6, n = idx & 63;
            int gn = n0 + n;
            if (gn < Ndim) {
                float v = Cs[m*68 + n];
#pragma unroll
                for (int k = 0; k < KE; ++k) v += sAt[m*16 + k]*sVe[k*64 + n];
                C[(size_t)(m0 + m)*ldc + gn] = v;
            }
        }
    } else {
        for (int idx = tid; idx < 128*64; idx += 256) {
            int m = idx >> 6, n = idx & 63;
            int gn = n0 + n;
            if (gn < Ndim)
                C[(size_t)(m0 + m)*ldc + gn] = Cs[m*68 + n];
        }
    }
}

template<int TB, int EPI, int HIN>
__global__ __launch_bounds__(256) void gemm_tf32(
        const float* __restrict__ A, const float* __restrict__ B,
        float* __restrict__ C,
        int Ndim, int Kdim, int lda, int ldb, int ldc,
        long aZ, long bZ, long cZ) {
    const float* Ao = HIN
        ? (const float*)((const __half*)A + (long)blockIdx.z*aZ)
        : (A + (long)blockIdx.z*aZ);
    gemm_body<TB, EPI, HIN>(Ao, B + (long)blockIdx.z*bZ,
                            C + (long)blockIdx.z*cZ,
                            Ndim, Kdim, lda, ldb, ldc,
                            blockIdx.y*128, blockIdx.x*64, blockIdx.z);
}

// ---------------------------------------------------------------------------
// Launch 1: fused prep — [0,768) wc, [768,840) Wkc, [840,912) Wv,
// [912,1104) Q-GEMM, [1104,1136) enc_qkv.
// ---------------------------------------------------------------------------
__global__ __launch_bounds__(256) void fused_prep(
        const float* __restrict__ kw, const float* __restrict__ lcw,
        const float* __restrict__ mixw, const float* __restrict__ s,
        const float* __restrict__ qw, const float* __restrict__ vw,
        const float* __restrict__ ellip, const float* __restrict__ eiw,
        const float* __restrict__ eib) {
    int bx = blockIdx.x;
    if (bx < 768) {
        int o = bx;
        int wg = threadIdx.x >> 5, l = threadIdx.x & 31;
        for (int m = wg; m < 9; m += 8) {
            float acc = 0.f;
            for (int j = l; j < DM; j += 32)
                acc += kw[(size_t)o*(2*DM) + DM + j]*lcw[j*9 + m];
            acc = warpSum(acc);
            if (l == 0) g_Wkc[(size_t)o*UD + DM + m] = acc;
        }
    } else if (bx < 840) {
        int idx = bx - 768;
        gemm_body<0,0,0>(kw, mixw, g_Wkc, DM, DM, 2*DM, DM, UD,
                         (idx/12)*128, (idx%12)*64, 0);
    } else if (bx < 912) {
        int idx = bx - 840;
        gemm_body<0,0,0>(vw, mixw, g_Wv, DM, DM, DM+DE, DM, DM,
                         (idx/12)*128, (idx%12)*64, 0);
    } else if (bx < 1104) {
        int idx = bx - 912;
        gemm_body<1,0,0>(s, qw, g_Q, DM, DM, DM, DM, DM,
                         (idx/12)*128, (idx%12)*64, 0);
    } else {
        extern __shared__ float smemq[];
        float* xs = smemq;
        int tk = bx - 1104;
        int tid = threadIdx.x, w = tid >> 5, l = tid & 31;
        if (tid < 32) ((float4*)xs)[tid] = ((const float4*)(ellip + tk*DE))[tid];
        __syncthreads();
        float4 xr = ((const float4*)xs)[l];
        for (int i = 0; i < 48; ++i) {
            int o = w*48 + i;
            float4 a = ((const float4*)(eiw + (size_t)o*DE))[l];
            float dot = warpSum(a.x*xr.x + a.y*xr.y + a.z*xr.z + a.w*xr.w);
            if (l == 0) g_encqkv[tk*3*DE + o] = dot + eib[o];
        }
    }
}

// ---------------------------------------------------------------------------
// enc_attn body (blocks 1664..1665 of launch 2) — dynamic smem.
// ---------------------------------------------------------------------------
__device__ void enc_attn_body(
        int b,
        const float* __restrict__ xin, const float* __restrict__ eow,
        const float* __restrict__ eob, const float* __restrict__ g1,
        const float* __restrict__ b1) {
    extern __shared__ float smema[];
    float (*qkv)[3*DE] = (float(*)[3*DE])smema;
    float (*ao)[DE]    = (float(*)[DE])(smema + KE*3*DE);
    float (*y)[DE]     = (float(*)[DE])(smema + KE*3*DE + KE*DE);
    int tid = threadIdx.x, w = tid >> 5, l = tid & 31;

    for (int idx = tid; idx < KE*3*DE; idx += 256)
        qkv[idx/(3*DE)][idx%(3*DE)] = g_encqkv[b*KE*3*DE + idx];
    __syncthreads();

#pragma unroll
    for (int pi = 0; pi < 8; ++pi) {
        int p = w*8 + pi;
        int h = p >> 4, q = p & 15;
        float qv = qkv[q][h*32 + l];
        float sc[KE];
#pragma unroll
        for (int k = 0; k < KE; ++k) {
            float pr = qv * qkv[k][DE + h*32 + l];
            sc[k] = warpSum(pr) * 0.17677669529f;
        }
        float mx = sc[0];
#pragma unroll
        for (int k = 1; k < KE; ++k) mx = fmaxf(mx, sc[k]);
        float ssum = 0.f;
#pragma unroll
        for (int k = 0; k < KE; ++k) { sc[k] = __expf(sc[k]-mx); ssum += sc[k]; }
        float inv = 1.f/ssum;
        float acc = 0.f;
#pragma unroll
        for (int k = 0; k < KE; ++k) acc += sc[k]*inv * qkv[k][2*DE + h*32 + l];
        ao[q][h*32 + l] = acc;
    }
    __syncthreads();

    for (int i = 0; i < 256; ++i) {
        int j = w*256 + i;
        int q = j >> 7, o = j & 127;
        float4 a = ((const float4*)(eow + (size_t)o*DE))[l];
        float4 x4 = ((const float4*)&ao[q][0])[l];
        float dot = warpSum(a.x*x4.x + a.y*x4.y + a.z*x4.z + a.w*x4.w);
        if (l == 0) y[q][o] = dot + eob[o] + xin[(b*KE + q)*DE + o];
    }
    __syncthreads();

#pragma unroll
    for (int qi = 0; qi < 2; ++qi) {
        int q = w*2 + qi;
        float v0 = y[q][l], v1 = y[q][l+32], v2 = y[q][l+64], v3 = y[q][l+96];
        float mean = warpSum(v0+v1+v2+v3) * (1.f/DE);
        float d0 = v0-mean, d1 = v1-mean, d2 = v2-mean, d3 = v3-mean;
        float var = warpSum(d0*d0+d1*d1+d2*d2+d3*d3) * (1.f/DE);
        float inv = rsqrtf(var + 1e-5f);
        g_x1[(b*KE+q)*DE + l]    = d0*inv*g1[l]    + b1[l];
        g_x1[(b*KE+q)*DE + l+32] = d1*inv*g1[l+32] + b1[l+32];
        g_x1[(b*KE+q)*DE + l+64] = d2*inv*g1[l+64] + b1[l+64];
        g_x1[(b*KE+q)*DE + l+96] = d3*inv*g1[l+96] + b1[l+96];
    }
}

// ---------------------------------------------------------------------------
// Launch 2: fused u-GEMM ([0,1664)) + enc_attn ([1664,1666))
// ---------------------------------------------------------------------------
__global__ __launch_bounds__(256) void fused_u(
        const float* __restrict__ xin, const float* __restrict__ eow,
        const float* __restrict__ eob, const float* __restrict__ g1,
        const float* __restrict__ b1) {
    int bx = blockIdx.x;
    if (bx < 1664) {
        int z = bx / 208, rem = bx % 208;
        gemm_body<0,0,0>(g_Q + z*DHD, g_Wkc + (size_t)z*DHD*UD, g_u + z*UD,
                         UD, DHD, DM, UD, NH*UD, (rem/13)*128, (rem%13)*64, z);
    } else {
        enc_attn_body(bx - 1664, xin, eow, eob, g1, b1);
    }
}

// ---------------------------------------------------------------------------
// enc_ff body (blocks 0..31 of merged launch 3)
// ---------------------------------------------------------------------------
__device__ void enc_ff_body(
        int tk,
        const float* __restrict__ l1w, const float* __restrict__ l1b,
        const float* __restrict__ l2w, const float* __restrict__ l2b,
        const float* __restrict__ g2,  const float* __restrict__ b2,
        const float* __restrict__ vw) {
    __shared__ float xs[DE];
    __shared__ float hs[ENCFF];
    __shared__ float es[DE];
    __shared__ float part[2][DE];
    __shared__ float red[8];
    __shared__ float smean, svar;
    int tid = threadIdx.x, w = tid >> 5, l = tid & 31;

    if (tid < 32) ((float4*)xs)[tid] = ((const float4*)(g_x1 + tk*DE))[tid];
    __syncthreads();
    float4 xr = ((const float4*)xs)[l];

    for (int i = 0; i < ENCFF/8; ++i) {
        int j = w*(ENCFF/8) + i;
        float4 a = ((const float4*)(l1w + (size_t)j*DE))[l];
        float dot = warpSum(a.x*xr.x + a.y*xr.y + a.z*xr.z + a.w*xr.w);
        if (l == 0) hs[j] = fmaxf(dot + l1b[j], 0.f);
    }
    __syncthreads();

    {
        int o = tid & 127, half = tid >> 7;
        const float4* wr4 = (const float4*)(l2w + (size_t)o*ENCFF + half*(ENCFF/2));
        const float4* hs4 = (const float4*)(hs + half*(ENCFF/2));
        float acc = 0.f;
#pragma unroll 4
        for (int j = 0; j < ENCFF/8; ++j) {
            float4 a = wr4[j], bq = hs4[j];
            acc += a.x*bq.x + a.y*bq.y + a.z*bq.z + a.w*bq.w;
        }
        part[half][o] = acc;
    }
    __syncthreads();
    if (tid < DE) es[tid] = part[0][tid] + part[1][tid] + l2b[tid] + xs[tid];
    __syncthreads();

    float val = (tid < DE) ? es[tid] : 0.f;
    float sr2 = warpSum(val);
    if (l == 0 && w < 4) red[w] = sr2;
    __syncthreads();
    if (tid == 0) smean = (red[0]+red[1]+red[2]+red[3]) * (1.f/DE);
    __syncthreads();
    float dv = (tid < DE) ? (es[tid]-smean) : 0.f;
    float s2 = warpSum(dv*dv);
    if (l == 0 && w < 4) red[w] = s2;
    __syncthreads();
    if (tid == 0) svar = (red[0]+red[1]+red[2]+red[3]) * (1.f/DE);
    __syncthreads();
    if (tid < DE) es[tid] = (es[tid]-smean)*rsqrtf(svar+1e-5f)*g2[tid] + b2[tid];
    __syncthreads();

    float4 er = ((const float4*)es)[l];
    for (int i = 0; i < DM/8; ++i) {
        int o = w*(DM/8) + i;
        float4 a = ((const float4*)(vw + (size_t)o*(DM+DE) + DM))[l];
        float dot = warpSum(a.x*er.x + a.y*er.y + a.z*er.z + a.w*er.w);
        if (l == 0) g_Ve[tk*DM + o] = dot;
    }
}

// ---------------------------------------------------------------------------
// Launch 3 (PROFILED): merged enc_ff (blocks [0,32)) + main_attn ([32,2080)).
// Natural regalloc; g written as fp16 (half2 pairs).
// ---------------------------------------------------------------------------
__global__ __launch_bounds__(256) void main_attn_kernel(
        const float* __restrict__ R, const float* __restrict__ t,
        const float* __restrict__ mu, const float* __restrict__ Sigma,
        const float* __restrict__ l1w, const float* __restrict__ l1b,
        const float* __restrict__ l2w, const float* __restrict__ l2b,
        const float* __restrict__ g2,  const float* __restrict__ b2,
        const float* __restrict__ vw) {
    if (blockIdx.x < FFBLK) {
        enc_ff_body(blockIdx.x, l1w, l1b, l2w, l2b, g2, b2, vw);
        return;
    }
    extern __shared__ float feat[];            // [KE][768]
    __shared__ float sR[9], sT[3];
    __shared__ float sr[KE][3];
    __shared__ float sC9[KE][9];
    __shared__ float sfreq[NFREQ];

    int row = blockIdx.x - FFBLK;
    int b = row >> 10;
    int tid = threadIdx.x, w = tid >> 5, l = tid & 31;

    if (tid < 9)  sR[tid] = R[(size_t)row*9 + tid];
    if (tid >= 16 && tid < 19) sT[tid-16] = t[(size_t)row*3 + (tid-16)];
    if (tid >= 128 && tid < 256) sfreq[tid-128] = exp2f(7.0f*(float)(tid-128)/127.0f);
    __syncthreads();

    if (tid < KE) {
        int k = tid;
        float d0 = mu[(b*KE+k)*3+0] - sT[0];
        float d1 = mu[(b*KE+k)*3+1] - sT[1];
        float d2 = mu[(b*KE+k)*3+2] - sT[2];
#pragma unroll
        for (int i = 0; i < 3; ++i)
            sr[k][i] = sR[0*3+i]*d0 + sR[1*3+i]*d1 + sR[2*3+i]*d2;
        float Sg[9];
#pragma unroll
        for (int jj = 0; jj < 9; ++jj) Sg[jj] = Sigma[(b*KE+k)*9 + jj];
        float M1[9];
#pragma unroll
        for (int j = 0; j < 3; ++j)
#pragma unroll
            for (int m = 0; m < 3; ++m)
                M1[j*3+m] = Sg[j*3+0]*sR[0*3+m] + Sg[j*3+1]*sR[1*3+m] + Sg[j*3+2]*sR[2*3+m];
#pragma unroll
        for (int i = 0; i < 3; ++i)
#pragma unroll
            for (int m = 0; m < 3; ++m)
                sC9[k][i*3+m] = sR[0*3+i]*M1[0*3+m] + sR[1*3+i]*M1[1*3+m] + sR[2*3+i]*M1[2*3+m];
    }
    __syncthreads();

    for (int idx = tid; idx < KE*384; idx += 256) {
        int k = idx / 384;
        int jj = idx - k*384;
        int c = jj >> 7, f = jj & 127;
        float sv, cv;
        __sincosf(sr[k][c]*sfreq[f], &sv, &cv);
        feat[k*DM + jj]       = sv;
        feat[k*DM + 384 + jj] = cv;
    }
    __syncthreads();

    int h = w;
    const float* ubase = g_u + ((size_t)row*NH + h)*UD;
    float4 ur4[6];
    const float4* up4 = (const float4*)ubase;
#pragma unroll
    for (int m = 0; m < 6; ++m) ur4[m] = up4[l + m*32];
    float qcr[9];
#pragma unroll
    for (int m = 0; m < 9; ++m) qcr[m] = ubase[DM + m];

    float sc[KE];
#pragma unroll
    for (int k = 0; k < KE; ++k) {
        const float4* fk4 = (const float4*)(feat + k*DM);
        float p = 0.f;
#pragma unroll
        for (int m = 0; m < 6; ++m) {
            float4 f = fk4[l + m*32];
            float4 u = ur4[m];
            p += u.x*f.x + u.y*f.y + u.z*f.z + u.w*f.w;
        }
        p = warpSum(p);
        float cv = 0.f;
#pragma unroll
        for (int mm = 0; mm < 9; ++mm) cv += qcr[mm]*sC9[k][mm];
        sc[k] = (p + cv) * 0.10206207262f;
    }
    float mx = sc[0];
#pragma unroll
    for (int k = 1; k < KE; ++k) mx = fmaxf(mx, sc[k]);
    float ssum = 0.f;
#pragma unroll
    for (int k = 0; k < KE; ++k) { sc[k] = __expf(sc[k]-mx); ssum += sc[k]; }
    float inv = 1.f/ssum;
#pragma unroll
    for (int k = 0; k < KE; ++k) sc[k] *= inv;

    if (l == 0) {
#pragma unroll
        for (int k = 0; k < KE; ++k)
            g_attn[(size_t)row*(NH*KE) + h*KE + k] = sc[k];
    }

    // g written as fp16 (element j = 4l + 128m, 4 consecutive halfs = 8B)
    __half* gh = g_gacc + ((size_t)row*NH + h)*DM;
#pragma unroll
    for (int m = 0; m < 6; ++m) {
        float4 acc = make_float4(0.f, 0.f, 0.f, 0.f);
#pragma unroll
        for (int k = 0; k < KE; ++k) {
            const float4 f = ((const float4*)(feat + k*DM))[l + m*32];
            float a = sc[k];
            acc.x += a*f.x; acc.y += a*f.y; acc.z += a*f.z; acc.w += a*f.w;
        }
        __half2 h01 = __floats2half2_rn(acc.x, acc.y);
        __half2 h23 = __floats2half2_rn(acc.z, acc.w);
        uint2 st;
        st.x = *(unsigned int*)&h01;
        st.y = *(unsigned int*)&h23;
        *(uint2*)(gh + 4*l + 128*m) = st;
    }
}

// ---------------------------------------------------------------------------
extern "C" void kernel_launch(void* const* d_in, const int* in_sizes, int n_in,
                              void* d_out, int out_size) {
    const float* s     = (const float*)d_in[0];
    const float* Rm    = (const float*)d_in[1];
    const float* t     = (const float*)d_in[2];
    const float* ellip = (const float*)d_in[3];
    const float* mu    = (const float*)d_in[4];
    const float* Sigma = (const float*)d_in[5];
    int off = (in_sizes[6] == BATCH*KE) ? 1 : 0;
    const float* mix_w     = (const float*)d_in[6+off];
    const float* lin_cov_w = (const float*)d_in[7+off];
    const float* q_w       = (const float*)d_in[8+off];
    const float* k_w       = (const float*)d_in[9+off];
    const float* v_w       = (const float*)d_in[10+off];
    const float* o_w       = (const float*)d_in[11+off];
    const float* enc_in_w  = (const float*)d_in[12+off];
    const float* enc_in_b  = (const float*)d_in[13+off];
    const float* enc_out_w = (const float*)d_in[14+off];
    const float* enc_out_b = (const float*)d_in[15+off];
    const float* lin1_w    = (const float*)d_in[16+off];
    const float* lin1_b    = (const float*)d_in[17+off];
    const float* lin2_w    = (const float*)d_in[18+off];
    const float* lin2_b    = (const float*)d_in[19+off];
    const float* ln1_g     = (const float*)d_in[20+off];
    const float* ln1_b     = (const float*)d_in[21+off];
    const float* ln2_g     = (const float*)d_in[22+off];
    const float* ln2_b     = (const float*)d_in[23+off];
    float* out = (float*)d_out;

    float *pWv, *pVp;
    __half* pG;
    cudaGetSymbolAddress((void**)&pG,  g_gacc);
    cudaGetSymbolAddress((void**)&pWv, g_Wv);
    cudaGetSymbolAddress((void**)&pVp, g_Vp);

    cudaFuncSetAttribute(main_attn_kernel,
                         cudaFuncAttributeMaxDynamicSharedMemorySize, KE*DM*4);

    // 1: wc + Wkc + Wv + Q + enc_qkv
    fused_prep<<<1136, 256, GEMM_SMEM_BYTES>>>(
        k_w, lin_cov_w, mix_w, s, q_w, v_w, ellip, enc_in_w, enc_in_b);
    // 2: u-GEMM + enc_attn
    fused_u<<<1666, 256, UATTN_SMEM_BYTES>>>(
        ellip, enc_out_w, enc_out_b, ln1_g, ln1_b);
    // 3 (PROFILED): enc_ff (front) + main attention
    main_attn_kernel<<<ROWS + FFBLK, 256, KE*DM*4>>>(
        Rm, t, mu, Sigma, lin1_w, lin1_b, lin2_w, lin2_b, ln2_g, ln2_b, v_w);
    // 4: Vp_h = g_h(fp16) @ Wv_h^T + Vec (epilogue)
    gemm_tf32<1,1,1><<<dim3(2,16,NH), 256, EPI_SMEM_BYTES>>>(
        (const float*)pG, pWv, pVp, DHD, DM, NH*DM, DM, DM,
        (long)DM, (long)DHD*DM, (long)DHD);
    // 5: out = Vp @ o_w^T
    gemm_tf32<1,0,0><<<dim3(12,16,1), 256, GEMM_SMEM_BYTES>>>(
        pVp, o_w, out, DM, DM, DM, DM, DM, 0, 0, 0);
    (void)n_in; (void)out_size;
}